// round 1
// baseline (speedup 1.0000x reference)
#include <cuda_runtime.h>

#define B_   32
#define C_   3
#define T_   4096
#define V_   25
#define P_   1024
#define O_   128
#define K_   24      // 3 channels * 8 patch samples
#define F_   28      // wavelet features per channel
#define PT   16      // patches per block
#define NT   (4*PT + 4)   // time samples needed per block (68)
#define TPB  256

// Fused projection matrix: G[o][c*8+j] maps raw patch samples -> output channel o
__device__ float g_G[O_ * K_];

// ---------------------------------------------------------------------------
// Setup kernel: build M (28x8, 2-level symmetric DWT of an 8-sample patch)
// and fuse with W: G = W @ blockdiag(M,M,M).  1 block, 128 threads.
// ---------------------------------------------------------------------------
__global__ void build_G(const float* __restrict__ W) {
    __shared__ float sM[F_][8];
    int tid = threadIdx.x;

    if (tid == 0) {
        const float DEC_LO[8] = {
            -0.010597401784997278f,  0.032883011666982945f,
             0.030841381835986965f, -0.18703481171888114f,
            -0.02798376941698385f,   0.6308807679295904f,
             0.7148465705525415f,    0.23037781330885523f };
        const float DEC_HI[8] = {
            -0.23037781330885523f,   0.7148465705525415f,
            -0.6308807679295904f,   -0.02798376941698385f,
             0.18703481171888114f,   0.030841381835986965f,
            -0.032883011666982945f, -0.010597401784997278f };

        float lo[8], hi[8];
        for (int j = 0; j < 8; j++) { lo[j] = DEC_LO[7 - j]; hi[j] = DEC_HI[7 - j]; }

        // Level 1: length-8 signal, symmetric ext, out index i: src = 2i+j-6
        float A1[7][8], D1[7][8];
        for (int i = 0; i < 7; i++)
            for (int k = 0; k < 8; k++) { A1[i][k] = 0.f; D1[i][k] = 0.f; }
        for (int i = 0; i < 7; i++)
            for (int j = 0; j < 8; j++) {
                int s = 2 * i + j - 6;
                if (s < 0)  s = -1 - s;
                if (s >= 8) s = 15 - s;
                A1[i][s] += lo[j];
                D1[i][s] += hi[j];
            }
        // Level 2: length-7 signal
        float L2l[7][7], L2h[7][7];
        for (int i = 0; i < 7; i++)
            for (int m = 0; m < 7; m++) { L2l[i][m] = 0.f; L2h[i][m] = 0.f; }
        for (int i = 0; i < 7; i++)
            for (int j = 0; j < 8; j++) {
                int s = 2 * i + j - 6;
                if (s < 0)  s = -1 - s;
                if (s >= 7) s = 13 - s;
                L2l[i][s] += lo[j];
                L2h[i][s] += hi[j];
            }
        // Feature order in reference: [aa, ad, dd, da]
        for (int i = 0; i < 7; i++)
            for (int k = 0; k < 8; k++) {
                float aa = 0.f, ad = 0.f, da = 0.f, dd = 0.f;
                for (int m = 0; m < 7; m++) {
                    aa += L2l[i][m] * A1[m][k];
                    ad += L2h[i][m] * A1[m][k];
                    da += L2l[i][m] * D1[m][k];
                    dd += L2h[i][m] * D1[m][k];
                }
                sM[i][k]      = aa;
                sM[7 + i][k]  = ad;
                sM[14 + i][k] = dd;
                sM[21 + i][k] = da;
            }
    }
    __syncthreads();

    int o = tid;  // 128 threads = 128 output channels
    for (int c = 0; c < C_; c++)
        for (int k = 0; k < 8; k++) {
            float g = 0.f;
            for (int f = 0; f < F_; f++)
                g += W[o * (C_ * F_) + c * F_ + f] * sM[f][k];
            g_G[o * K_ + c * 8 + k] = g;
        }
}

// ---------------------------------------------------------------------------
// Main kernel: out[b, v*P+p, o] = sum_{c,j} G[o][c*8+j] * x_clamped[b,c,4p+j,v]
// Block = (batch b, 16-patch tile). 256 threads:
//   tid%32 = o-group (4 consecutive output channels), tid/32 = position group.
// All 32 lanes of a warp share the same (v,pl) -> smem reads are broadcasts,
// stores are 512B contiguous per warp.
// ---------------------------------------------------------------------------
__global__ void __launch_bounds__(TPB, 2)
wavelet_gemm(const float* __restrict__ x, float* __restrict__ out) {
    __shared__ float xs[C_][NT][V_];   // 3*68*25*4 = 20400 B

    const int b   = blockIdx.y;
    const int pt0 = blockIdx.x * PT;
    const int t0  = 4 * pt0;
    const int tid = threadIdx.x;

    // --- stage x tile: fully coalesced (t,v) contiguous per channel ---
    const float* xb = x + (size_t)b * C_ * T_ * V_;
    const int tot = C_ * NT * V_;  // 5100
    for (int idx = tid; idx < tot; idx += TPB) {
        int c  = idx / (NT * V_);
        int r  = idx - c * (NT * V_);
        int tl = r / V_;
        int v  = r - tl * V_;
        int t  = t0 + tl;
        if (t > T_ - 1) t = T_ - 1;      // edge padding
        xs[c][tl][v] = xb[(c * T_ + t) * V_ + v];
    }

    // --- each thread holds 4 rows of G in registers ---
    const int og = tid & 31;
    const int pg = tid >> 5;
    float g[4][K_];
#pragma unroll
    for (int i = 0; i < 4; i++)
#pragma unroll
        for (int k = 0; k < K_; k++)
            g[i][k] = g_G[(og * 4 + i) * K_ + k];

    __syncthreads();

    // positions: (v, pl), v in [0,25), pl in [0,16). 400 total, 8 pos groups.
    for (int it = 0; it < (V_ * PT) / 8; it++) {
        int pos = it * 8 + pg;
        int v   = pos >> 4;      // / PT
        int pl  = pos & 15;      // % PT

        float a0 = 0.f, a1 = 0.f, a2 = 0.f, a3 = 0.f;
#pragma unroll
        for (int k = 0; k < K_; k++) {
            int c = k >> 3;
            int j = k & 7;
            float xv = xs[c][4 * pl + j][v];   // warp-uniform -> broadcast
            a0 = fmaf(g[0][k], xv, a0);
            a1 = fmaf(g[1][k], xv, a1);
            a2 = fmaf(g[2][k], xv, a2);
            a3 = fmaf(g[3][k], xv, a3);
        }
        size_t obase = (((size_t)b * V_ + v) * P_ + (pt0 + pl)) * (size_t)O_ + og * 4;
        *reinterpret_cast<float4*>(out + obase) = make_float4(a0, a1, a2, a3);
    }
}

// ---------------------------------------------------------------------------
extern "C" void kernel_launch(void* const* d_in, const int* in_sizes, int n_in,
                              void* d_out, int out_size) {
    const float* x = (const float*)d_in[0];
    const float* W = (const float*)d_in[1];
    // defensive: x has 9,830,400 elems, W has 10,752 — swap if order differs
    if (n_in >= 2 && in_sizes[0] < in_sizes[1]) {
        const float* t = x; x = W; W = t;
    }

    build_G<<<1, 128>>>(W);

    dim3 grid(P_ / PT, B_);
    wavelet_gemm<<<grid, TPB>>>(x, (float*)d_out);
}

// round 2
// speedup vs baseline: 1.0222x; 1.0222x over previous
#include <cuda_runtime.h>

#define B_   32
#define C_   3
#define T_   4096
#define V_   25
#define P_   1024
#define O_   128
#define K_   24      // 3 channels * 8 patch samples
#define F_   28      // wavelet features per channel
#define PT   16      // patches per block
#define NT   (4*PT + 4)   // time samples needed per block (68)
#define NTP  70            // padded (even, mild bank-conflict relief)
#define TPB  256

// Fused projection matrix: G[o][c*8+j] maps raw patch samples -> output channel o
__device__ float g_G[O_ * K_];

// ---------------------------------------------------------------------------
// Setup kernel: build M (28x8, 2-level symmetric DWT of an 8-sample patch)
// and fuse with W: G = W @ blockdiag(M,M,M).  1 block, 128 threads.
// ---------------------------------------------------------------------------
__global__ void build_G(const float* __restrict__ W) {
    __shared__ float sM[F_][8];
    int tid = threadIdx.x;

    if (tid == 0) {
        const float DEC_LO[8] = {
            -0.010597401784997278f,  0.032883011666982945f,
             0.030841381835986965f, -0.18703481171888114f,
            -0.02798376941698385f,   0.6308807679295904f,
             0.7148465705525415f,    0.23037781330885523f };
        const float DEC_HI[8] = {
            -0.23037781330885523f,   0.7148465705525415f,
            -0.6308807679295904f,   -0.02798376941698385f,
             0.18703481171888114f,   0.030841381835986965f,
            -0.032883011666982945f, -0.010597401784997278f };

        float lo[8], hi[8];
        for (int j = 0; j < 8; j++) { lo[j] = DEC_LO[7 - j]; hi[j] = DEC_HI[7 - j]; }

        // Level 1: length-8 signal, symmetric ext, out index i: src = 2i+j-6
        float A1[7][8], D1[7][8];
        for (int i = 0; i < 7; i++)
            for (int k = 0; k < 8; k++) { A1[i][k] = 0.f; D1[i][k] = 0.f; }
        for (int i = 0; i < 7; i++)
            for (int j = 0; j < 8; j++) {
                int s = 2 * i + j - 6;
                if (s < 0)  s = -1 - s;
                if (s >= 8) s = 15 - s;
                A1[i][s] += lo[j];
                D1[i][s] += hi[j];
            }
        // Level 2: length-7 signal
        float L2l[7][7], L2h[7][7];
        for (int i = 0; i < 7; i++)
            for (int m = 0; m < 7; m++) { L2l[i][m] = 0.f; L2h[i][m] = 0.f; }
        for (int i = 0; i < 7; i++)
            for (int j = 0; j < 8; j++) {
                int s = 2 * i + j - 6;
                if (s < 0)  s = -1 - s;
                if (s >= 7) s = 13 - s;
                L2l[i][s] += lo[j];
                L2h[i][s] += hi[j];
            }
        // Feature order in reference: [aa, ad, dd, da]
        for (int i = 0; i < 7; i++)
            for (int k = 0; k < 8; k++) {
                float aa = 0.f, ad = 0.f, da = 0.f, dd = 0.f;
                for (int m = 0; m < 7; m++) {
                    aa += L2l[i][m] * A1[m][k];
                    ad += L2h[i][m] * A1[m][k];
                    da += L2l[i][m] * D1[m][k];
                    dd += L2h[i][m] * D1[m][k];
                }
                sM[i][k]      = aa;
                sM[7 + i][k]  = ad;
                sM[14 + i][k] = dd;
                sM[21 + i][k] = da;
            }
    }
    __syncthreads();

    int o = tid;  // 128 threads = 128 output channels
    for (int c = 0; c < C_; c++)
        for (int k = 0; k < 8; k++) {
            float g = 0.f;
            for (int f = 0; f < F_; f++)
                g += W[o * (C_ * F_) + c * F_ + f] * sM[f][k];
            g_G[o * K_ + c * 8 + k] = g;
        }
}

// ---------------------------------------------------------------------------
// Main kernel, packed-f32x2 version.
// out[b, v*P+p, o] = sum_{c,j} G[o][c*8+j] * x_clamped[b,c,4p+j,v]
//
// smem holds the x tile DUPLICATED per element (float2(v,v)), time-contiguous,
// so one LDS.128 broadcast delivers two ready-to-use packed operands.
// Each thread owns 4 consecutive output channels as 2 packed accumulators and
// 48 packed G pairs; inner loop = 48 fma.rn.f32x2 + 12 LDS.128 + 1 STG.128.
// ---------------------------------------------------------------------------
typedef unsigned long long u64;

__global__ void __launch_bounds__(TPB, 2)
wavelet_gemm(const float* __restrict__ x, float* __restrict__ out) {
    __shared__ float2 xs2[C_][V_][NTP];   // 3*25*70*8 = 42000 B

    const int b   = blockIdx.y;
    const int pt0 = blockIdx.x * PT;
    const int t0  = 4 * pt0;
    const int tid = threadIdx.x;

    // --- stage x tile: coalesced global reads (v innermost), duplicated write ---
    const float* xb = x + (size_t)b * C_ * T_ * V_;
    const int tot = C_ * NT * V_;  // 5100
    for (int idx = tid; idx < tot; idx += TPB) {
        int c  = idx / (NT * V_);
        int r  = idx - c * (NT * V_);
        int tl = r / V_;
        int v  = r - tl * V_;
        int t  = t0 + tl;
        if (t > T_ - 1) t = T_ - 1;      // edge padding
        float val = xb[(c * T_ + t) * V_ + v];
        xs2[c][v][tl] = make_float2(val, val);
    }

    // --- each thread holds 4 rows of G as packed f32x2 pairs ---
    const int og = tid & 31;   // output group: channels og*4 .. og*4+3
    const int pg = tid >> 5;   // position group (warp id)

    u64 gA[K_], gB[K_];        // (o0,o1) and (o2,o3) packed per k
#pragma unroll
    for (int k = 0; k < K_; k++) {
        float a0 = g_G[(og * 4 + 0) * K_ + k];
        float a1 = g_G[(og * 4 + 1) * K_ + k];
        float a2 = g_G[(og * 4 + 2) * K_ + k];
        float a3 = g_G[(og * 4 + 3) * K_ + k];
        asm("mov.b64 %0, {%1, %2};" : "=l"(gA[k]) : "f"(a0), "f"(a1));
        asm("mov.b64 %0, {%1, %2};" : "=l"(gB[k]) : "f"(a2), "f"(a3));
    }

    __syncthreads();

    // positions: (v, pl), v in [0,25), pl in [0,16). 400 total, 8 pos groups.
#pragma unroll 1
    for (int it = 0; it < (V_ * PT) / 8; it++) {
        int pos = it * 8 + pg;
        int v   = pos >> 4;      // / PT
        int pl  = pos & 15;      // % PT

        u64 acc0 = 0ULL, acc1 = 0ULL;
#pragma unroll
        for (int c = 0; c < C_; c++) {
            const ulonglong2* xp =
                reinterpret_cast<const ulonglong2*>(&xs2[c][v][4 * pl]);
#pragma unroll
            for (int j2 = 0; j2 < 4; j2++) {
                ulonglong2 xx = xp[j2];          // LDS.128 broadcast, 2 dup pairs
                int k = c * 8 + 2 * j2;
                asm("fma.rn.f32x2 %0, %1, %2, %0;" : "+l"(acc0) : "l"(gA[k]),     "l"(xx.x));
                asm("fma.rn.f32x2 %0, %1, %2, %0;" : "+l"(acc1) : "l"(gB[k]),     "l"(xx.x));
                asm("fma.rn.f32x2 %0, %1, %2, %0;" : "+l"(acc0) : "l"(gA[k + 1]), "l"(xx.y));
                asm("fma.rn.f32x2 %0, %1, %2, %0;" : "+l"(acc1) : "l"(gB[k + 1]), "l"(xx.y));
            }
        }

        size_t obase = (((size_t)b * V_ + v) * P_ + (pt0 + pl)) * (size_t)O_ + og * 4;
        ulonglong2 res;
        res.x = acc0;   // bits: lo = o0, hi = o1 (little-endian float order)
        res.y = acc1;   // lo = o2, hi = o3
        *reinterpret_cast<ulonglong2*>(out + obase) = res;   // STG.128, 512B/warp
    }
}

// ---------------------------------------------------------------------------
extern "C" void kernel_launch(void* const* d_in, const int* in_sizes, int n_in,
                              void* d_out, int out_size) {
    const float* x = (const float*)d_in[0];
    const float* W = (const float*)d_in[1];
    if (n_in >= 2 && in_sizes[0] < in_sizes[1]) {
        const float* t = x; x = W; W = t;
    }

    build_G<<<1, 128>>>(W);

    dim3 grid(P_ / PT, B_);
    wavelet_gemm<<<grid, TPB>>>(x, (float*)d_out);
}

// round 3
// speedup vs baseline: 1.3269x; 1.2981x over previous
#include <cuda_runtime.h>

typedef unsigned long long u64;

#define B_   32
#define C_   3
#define T_   4096
#define V_   25
#define P_   1024
#define O_   128
#define K_   24      // 3 channels * 8 patch samples
#define F_   28      // wavelet features per channel

// ---------------------------------------------------------------------------
// Global scratch / constants (no cudaMalloc allowed)
// ---------------------------------------------------------------------------
__device__ float  g_G[O_ * K_];            // fused projection, [o][k]
__device__ float2 g_Gd[K_ * O_];           // duplicated pairs, [k][o] = (g,g)
__device__ float  g_xT[(size_t)B_ * V_ * K_ * P_];   // 78.6 MB transposed x

// ---------------------------------------------------------------------------
// Setup: build M (28x8, 2-level symmetric DWT of an 8-sample patch) and fuse
// with W: G = W @ blockdiag(M,M,M).  1 block, 128 threads.
// ---------------------------------------------------------------------------
__global__ void build_G(const float* __restrict__ W) {
    __shared__ float sM[F_][8];
    int tid = threadIdx.x;

    if (tid == 0) {
        const float DEC_LO[8] = {
            -0.010597401784997278f,  0.032883011666982945f,
             0.030841381835986965f, -0.18703481171888114f,
            -0.02798376941698385f,   0.6308807679295904f,
             0.7148465705525415f,    0.23037781330885523f };
        const float DEC_HI[8] = {
            -0.23037781330885523f,   0.7148465705525415f,
            -0.6308807679295904f,   -0.02798376941698385f,
             0.18703481171888114f,   0.030841381835986965f,
            -0.032883011666982945f, -0.010597401784997278f };

        float lo[8], hi[8];
        for (int j = 0; j < 8; j++) { lo[j] = DEC_LO[7 - j]; hi[j] = DEC_HI[7 - j]; }

        float A1[7][8], D1[7][8];
        for (int i = 0; i < 7; i++)
            for (int k = 0; k < 8; k++) { A1[i][k] = 0.f; D1[i][k] = 0.f; }
        for (int i = 0; i < 7; i++)
            for (int j = 0; j < 8; j++) {
                int s = 2 * i + j - 6;
                if (s < 0)  s = -1 - s;
                if (s >= 8) s = 15 - s;
                A1[i][s] += lo[j];
                D1[i][s] += hi[j];
            }
        float L2l[7][7], L2h[7][7];
        for (int i = 0; i < 7; i++)
            for (int m = 0; m < 7; m++) { L2l[i][m] = 0.f; L2h[i][m] = 0.f; }
        for (int i = 0; i < 7; i++)
            for (int j = 0; j < 8; j++) {
                int s = 2 * i + j - 6;
                if (s < 0)  s = -1 - s;
                if (s >= 7) s = 13 - s;
                L2l[i][s] += lo[j];
                L2h[i][s] += hi[j];
            }
        // Feature order in reference: [aa, ad, dd, da]
        for (int i = 0; i < 7; i++)
            for (int k = 0; k < 8; k++) {
                float aa = 0.f, ad = 0.f, da = 0.f, dd = 0.f;
                for (int m = 0; m < 7; m++) {
                    aa += L2l[i][m] * A1[m][k];
                    ad += L2h[i][m] * A1[m][k];
                    da += L2l[i][m] * D1[m][k];
                    dd += L2h[i][m] * D1[m][k];
                }
                sM[i][k]      = aa;
                sM[7 + i][k]  = ad;
                sM[14 + i][k] = dd;
                sM[21 + i][k] = da;
            }
    }
    __syncthreads();

    int o = tid;  // 128 threads = 128 output channels
    for (int c = 0; c < C_; c++)
        for (int k = 0; k < 8; k++) {
            float g = 0.f;
            for (int f = 0; f < F_; f++)
                g += W[o * (C_ * F_) + c * F_ + f] * sM[f][k];
            g_G[o * K_ + (c * 8 + k)] = g;
            g_Gd[(c * 8 + k) * O_ + o] = make_float2(g, g);
        }
}

// ---------------------------------------------------------------------------
// Kernel 1: transpose x -> xT[b][v][k][p]  (p contiguous), with edge padding.
// Block = (32-patch tile, batch). Coalesced global read, smem relay,
// fully coalesced 128B-run global writes.
// ---------------------------------------------------------------------------
#define PT1 32
#define NT1 (4*PT1 + 4)    // 132 time samples per tile

__global__ void __launch_bounds__(256)
transpose_x(const float* __restrict__ x) {
    __shared__ float xs[C_][NT1][V_];   // 39.6 KB

    const int b   = blockIdx.y;
    const int p0  = blockIdx.x * PT1;
    const int t0  = 4 * p0;
    const int tid = threadIdx.x;

    const float* xb = x + (size_t)b * C_ * T_ * V_;
    const int tot = C_ * NT1 * V_;      // 9900
    for (int idx = tid; idx < tot; idx += 256) {
        int c = idx / (NT1 * V_);
        int r = idx - c * (NT1 * V_);
        int t = t0 + r / V_;
        float val;
        if (t <= T_ - 1)
            val = xb[c * (T_ * V_) + t0 * V_ + r];          // contiguous fast path
        else
            val = xb[c * (T_ * V_) + (T_ - 1) * V_ + r % V_]; // edge pad
        (&xs[0][0][0])[c * (NT1 * V_) + r] = val;
    }
    __syncthreads();

    float* xTb = g_xT + (size_t)b * V_ * K_ * P_;
    const int tot2 = V_ * K_ * PT1;     // 19200
    for (int idx = tid; idx < tot2; idx += 256) {
        int p   = idx & (PT1 - 1);
        int rem = idx >> 5;             // /32
        int k   = rem % K_;
        int v   = rem / K_;
        int c   = k >> 3;
        int j   = k & 7;
        xTb[((size_t)v * K_ + k) * P_ + p0 + p] = xs[c][4 * p + j][v];
    }
}

// ---------------------------------------------------------------------------
// Kernel 2: GEMM  out[(b,v,p), o] = sum_k xT[b][v][k][p] * G[o][k]
// Block tile: 128 p x 128 ch. Thread: 8 p (4 f32x2 pairs) x 8 ch.
// Warp: lanes = 4 pos-groups x 8 ch-groups; 8 warps = 4 pos-slices x 2 ch-slices.
// x from contiguous LDG.128; dup-G from smem (pad-80B layout, conflict-free).
// ---------------------------------------------------------------------------
#define PTILE 128

__global__ void __launch_bounds__(256, 2)
wavelet_gemm2(float* __restrict__ out) {
    // gd[k][group of 8 ch][8 dup-pairs + 2 pad]  (80B group stride: 16B-aligned,
    // bank pattern og*20+c mod 32 -> all distinct across the 8 og lanes)
    __shared__ __align__(16) u64 gd[K_][16][10];   // 30720 B

    const int tid = threadIdx.x;

    // stage duplicated G (contiguous global read)
    for (int idx = tid; idx < K_ * O_; idx += 256) {
        int o = idx & (O_ - 1);
        int k = idx >> 7;
        const float2 d = g_Gd[idx];
        gd[k][o >> 3][o & 7] = *reinterpret_cast<const u64*>(&d);
    }
    __syncthreads();

    const int b   = blockIdx.z;
    const int v   = blockIdx.y;
    const int pt0 = blockIdx.x * PTILE;

    const int lane = tid & 31, wrp = tid >> 5;
    const int og = lane & 7,  pg  = lane >> 3;   // 8 ch-groups x 4 pos-groups
    const int ps = wrp & 3,   chs = wrp >> 2;    // 4 pos-slices x 2 ch-slices
    const int p0  = ps * 32 + pg * 8;            // 8 consecutive p
    const int ch0 = chs * 64 + og * 8;           // 8 consecutive ch
    const int grp = ch0 >> 3;

    const float* xrow = g_xT + ((size_t)(b * V_ + v) * K_) * P_ + pt0 + p0;

    u64 acc[4][8];
#pragma unroll
    for (int pp = 0; pp < 4; pp++)
#pragma unroll
        for (int c = 0; c < 8; c++) acc[pp][c] = 0ULL;

#pragma unroll
    for (int k = 0; k < K_; k++) {
        const float* xk = xrow + k * P_;
        ulonglong2 xa = *reinterpret_cast<const ulonglong2*>(xk);      // p pairs 0,1
        ulonglong2 xc = *reinterpret_cast<const ulonglong2*>(xk + 4);  // p pairs 2,3
        u64 xp[4] = { xa.x, xa.y, xc.x, xc.y };

        const ulonglong2* gp = reinterpret_cast<const ulonglong2*>(&gd[k][grp][0]);
        ulonglong2 g01 = gp[0], g23 = gp[1], g45 = gp[2], g67 = gp[3];
        u64 gv[8] = { g01.x, g01.y, g23.x, g23.y, g45.x, g45.y, g67.x, g67.y };

#pragma unroll
        for (int pp = 0; pp < 4; pp++)
#pragma unroll
            for (int c = 0; c < 8; c++)
                asm("fma.rn.f32x2 %0, %1, %2, %0;"
                    : "+l"(acc[pp][c]) : "l"(gv[c]), "l"(xp[pp]));
    }

    float* orow = out + (((size_t)(b * V_ + v) * P_ + pt0 + p0) << 7) + ch0;
#pragma unroll
    for (int pp = 0; pp < 4; pp++) {
        float lo[8], hi[8];
#pragma unroll
        for (int c = 0; c < 8; c++)
            asm("mov.b64 {%0, %1}, %2;" : "=f"(lo[c]), "=f"(hi[c]) : "l"(acc[pp][c]));
        float* r0 = orow + (size_t)(2 * pp) * O_;
        *reinterpret_cast<float4*>(r0)          = make_float4(lo[0], lo[1], lo[2], lo[3]);
        *reinterpret_cast<float4*>(r0 + 4)      = make_float4(lo[4], lo[5], lo[6], lo[7]);
        *reinterpret_cast<float4*>(r0 + O_)     = make_float4(hi[0], hi[1], hi[2], hi[3]);
        *reinterpret_cast<float4*>(r0 + O_ + 4) = make_float4(hi[4], hi[5], hi[6], hi[7]);
    }
}

// ---------------------------------------------------------------------------
extern "C" void kernel_launch(void* const* d_in, const int* in_sizes, int n_in,
                              void* d_out, int out_size) {
    const float* x = (const float*)d_in[0];
    const float* W = (const float*)d_in[1];
    if (n_in >= 2 && in_sizes[0] < in_sizes[1]) {
        const float* t = x; x = W; W = t;
    }

    build_G<<<1, 128>>>(W);

    dim3 g1(P_ / PT1, B_);
    transpose_x<<<g1, 256>>>(x);

    dim3 g2(P_ / PTILE, V_, B_);
    wavelet_gemm2<<<g2, 256>>>((float*)d_out);
}